// round 16
// baseline (speedup 1.0000x reference)
#include <cuda_runtime.h>
#include <cuda_fp16.h>
#include <cstdint>

#define N_NODES 50000
#define N_EDGES 800000
#define TOT_ADJ (N_EDGES + N_NODES)
#define HID 512           // HEADS*OUT_CH
#define IN_CH 128
#define OUT_CH 128
#define HEADS 4
#define NEG_SLOPE 0.2f
#define LN_EPS 1e-5f
#define CAP 256
#define SCAN_BLK 256
#define NPART ((N_NODES + SCAN_BLK - 1) / SCAN_BLK)   // 196

// ---------------- device scratch (static, no allocation) ----------------
__device__ __half g_h16[(size_t)N_NODES * HID];    // h  (fp16, 51 MB, ~L2-resident)
__device__ __half g_act16[(size_t)N_NODES * HID];  // relu(agg + gat_bias) fp16
__device__ __half2 g_w16[(HID / 2) * OUT_CH];      // proj_w, k-pair packed fp16
__device__ __half2 g_lw16[(IN_CH / 2) * HID];      // lin_w, k-pair packed fp16
__device__ float g_asrc[N_NODES * HEADS];
__device__ float g_adst[N_NODES * HEADS];
__device__ int   g_cnt[N_NODES];
__device__ int   g_cur[N_NODES];
__device__ int   g_off[N_NODES + 1];
__device__ int   g_adj[TOT_ADJ];
__device__ int   g_part[NPART];
__device__ int   g_is64;

// ---------------- dtype probe (1 block, parallel strided sample) --------
__global__ void detect_k(const void* ei) {
    const long long* p = (const long long*)ei;
    int ok = 1;
    for (int j = (int)threadIdx.x; j < 1024; j += 256) {
        long long v = p[j * 3];
        if (v < 0 || v >= N_NODES) ok = 0;
    }
    ok = __all_sync(0xffffffffu, ok);
    __shared__ int sok[8];
    if ((threadIdx.x & 31) == 0) sok[threadIdx.x >> 5] = ok;
    __syncthreads();
    if (threadIdx.x == 0) {
        int r = 1;
#pragma unroll
        for (int q = 0; q < 8; q++) r &= sok[q];
        g_is64 = r;
    }
}

__device__ __forceinline__ int load_idx(const void* ei, size_t pos, int is64) {
    if (is64) return (int)((const long long*)ei)[pos];
    return ((const int*)ei)[pos];
}

__global__ void hist_k(const void* ei) {
    int i = blockIdx.x * blockDim.x + threadIdx.x;
    if (i >= N_EDGES) return;
    int d = load_idx(ei, (size_t)N_EDGES + i, g_is64);
    atomicAdd(&g_cnt[d], 1);
}

__global__ void partial_k() {
    __shared__ int sd[SCAN_BLK];
    int i = blockIdx.x * SCAN_BLK + threadIdx.x;
    sd[threadIdx.x] = (i < N_NODES) ? g_cnt[i] : 0;
    __syncthreads();
    for (int st = SCAN_BLK / 2; st; st >>= 1) {
        if (threadIdx.x < st) sd[threadIdx.x] += sd[threadIdx.x + st];
        __syncthreads();
    }
    if (threadIdx.x == 0) g_part[blockIdx.x] = sd[0];
}

// fused: per-block base + local scan + offsets + self-loop seed.
// off[i] = edge_prefix(i) + i  (the +i covers self loops).
__global__ void scanoff_k() {
    __shared__ int sd[SCAN_BLK];
    __shared__ int sbase;
    int tid = threadIdx.x;
    int i = blockIdx.x * SCAN_BLK + tid;

    if (tid < 32) {
        int s = 0;
        for (int j = tid; j < blockIdx.x; j += 32) s += g_part[j];
#pragma unroll
        for (int o = 16; o; o >>= 1) s += __shfl_xor_sync(0xffffffffu, s, o);
        if (tid == 0) sbase = s;
    }

    int own = (i < N_NODES) ? g_cnt[i] : 0;
    sd[tid] = own;
    __syncthreads();
    for (int st = 1; st < SCAN_BLK; st <<= 1) {
        int v = (tid >= st) ? sd[tid - st] : 0;
        __syncthreads();
        sd[tid] += v;
        __syncthreads();
    }
    if (i < N_NODES) {
        int off = sbase + (sd[tid] - own) + i;
        g_off[i] = off;
        g_adj[off] = i;      // self loop first
        g_cur[i] = 1;
        if (i == N_NODES - 1) g_off[N_NODES] = off + own + 1;
    }
}

__global__ void scatter_k(const void* ei) {
    int i = blockIdx.x * blockDim.x + threadIdx.x;
    if (i >= N_EDGES) return;
    int is64 = g_is64;
    int s = load_idx(ei, (size_t)i, is64);
    int d = load_idx(ei, (size_t)N_EDGES + i, is64);
    int pos = g_off[d] + atomicAdd(&g_cur[d], 1);
    g_adj[pos] = s;
}

// ---------------- weight packs: k-pair fp16 ------------------------------
__global__ void wconv_k(const float* __restrict__ w) {
    int i = blockIdx.x * blockDim.x + threadIdx.x;   // kp*128 + n
    if (i >= (HID / 2) * OUT_CH) return;
    int kp = i >> 7, n = i & 127;
    g_w16[i] = __floats2half2_rn(w[(2 * kp) * OUT_CH + n],
                                 w[(2 * kp + 1) * OUT_CH + n]);
}

__global__ void lwconv_k(const float* __restrict__ w) {
    int i = blockIdx.x * blockDim.x + threadIdx.x;   // kp*512 + n
    if (i >= (IN_CH / 2) * HID) return;
    int kp = i >> 9, n = i & 511;
    g_lw16[i] = __floats2half2_rn(w[(2 * kp) * HID + n],
                                  w[(2 * kp + 1) * HID + n]);
}

// ---- GEMM1: one block per 64 rows, loops all 8 N-tiles, sA resident ----
__global__ __launch_bounds__(256) void gemm1_k(const float* __restrict__ x,
                                               const float* __restrict__ att_src,
                                               const float* __restrict__ att_dst) {
    __shared__ uint32_t sA[64 * 68];    // 17 KB
    __shared__ uint32_t sB[64 * 72];    // 18 KB
    __shared__ float sRs[64][4], sRd[64][4];   // 2 KB cross-warp_n combine
    int tid = threadIdx.x;
    int lane = tid & 31, wid = tid >> 5;
    int warp_m = wid & 3, warp_n = wid >> 2;
    int m0 = blockIdx.x * 64;

#pragma unroll
    for (int p = 0; p < 8; p++) {
        int idx = tid + p * 256;
        int row = idx >> 5, kp = (idx & 31) * 2;
        int gr = m0 + row;
        float4 v = (gr < N_NODES) ? *(const float4*)&x[(size_t)gr * 128 + kp * 2]
                                  : make_float4(0.f, 0.f, 0.f, 0.f);
        __half2 h0 = __floats2half2_rn(v.x, v.y);
        __half2 h1 = __floats2half2_rn(v.z, v.w);
        sA[row * 68 + kp]     = *(uint32_t*)&h0;
        sA[row * 68 + kp + 1] = *(uint32_t*)&h1;
    }

    int aRow = warp_m * 16 + (lane >> 2);
    int kq = lane & 3;
    int rowA = m0 + aRow;

    float psA[4] = {0.f, 0.f, 0.f, 0.f}, psB[4] = {0.f, 0.f, 0.f, 0.f};
    float pdA[4] = {0.f, 0.f, 0.f, 0.f}, pdB[4] = {0.f, 0.f, 0.f, 0.f};

#pragma unroll
    for (int t = 0; t < 8; t++) {
        int n0 = t * 64;
        int head = t >> 1;
        __syncthreads();
#pragma unroll
        for (int p = 0; p < 4; p++) {
            int idx = tid + p * 256;
            int kp = idx >> 4, q = (idx & 15) * 4;
            uint4 v = *(const uint4*)&g_lw16[(size_t)kp * HID + n0 + q];
            *(uint4*)&sB[kp * 72 + q] = v;
        }
        __syncthreads();

        float c[4][4];
#pragma unroll
        for (int nt = 0; nt < 4; nt++)
#pragma unroll
            for (int r = 0; r < 4; r++) c[nt][r] = 0.f;

#pragma unroll
        for (int ks = 0; ks < 8; ks++) {
            int o = ks * 8;
            uint32_t a0 = sA[aRow * 68 + o + kq];
            uint32_t a1 = sA[(aRow + 8) * 68 + o + kq];
            uint32_t a2 = sA[aRow * 68 + o + kq + 4];
            uint32_t a3 = sA[(aRow + 8) * 68 + o + kq + 4];
#pragma unroll
            for (int nt = 0; nt < 4; nt++) {
                int nb = warp_n * 32 + nt * 8 + (lane >> 2);
                uint32_t b0 = sB[(o + kq) * 72 + nb];
                uint32_t b1 = sB[(o + kq + 4) * 72 + nb];
                asm volatile(
                    "mma.sync.aligned.m16n8k16.row.col.f32.f16.f16.f32 "
                    "{%0,%1,%2,%3}, {%4,%5,%6,%7}, {%8,%9}, {%0,%1,%2,%3};"
                    : "+f"(c[nt][0]), "+f"(c[nt][1]), "+f"(c[nt][2]), "+f"(c[nt][3])
                    : "r"(a0), "r"(a1), "r"(a2), "r"(a3), "r"(b0), "r"(b1));
            }
        }

#pragma unroll
        for (int nt = 0; nt < 4; nt++) {
            int col = n0 + warp_n * 32 + nt * 8 + (lane & 3) * 2;
            if (rowA < N_NODES)
                *(__half2*)&g_h16[(size_t)rowA * HID + col] =
                    __floats2half2_rn(c[nt][0], c[nt][1]);
            if (rowA + 8 < N_NODES)
                *(__half2*)&g_h16[(size_t)(rowA + 8) * HID + col] =
                    __floats2half2_rn(c[nt][2], c[nt][3]);
            int cc = col & 127;
            float s0 = att_src[head * 128 + cc], s1 = att_src[head * 128 + cc + 1];
            float d0 = att_dst[head * 128 + cc], d1 = att_dst[head * 128 + cc + 1];
            psA[head] += c[nt][0] * s0 + c[nt][1] * s1;
            pdA[head] += c[nt][0] * d0 + c[nt][1] * d1;
            psB[head] += c[nt][2] * s0 + c[nt][3] * s1;
            pdB[head] += c[nt][2] * d0 + c[nt][3] * d1;
        }
    }

#pragma unroll
    for (int h = 0; h < 4; h++) {
#pragma unroll
        for (int o = 1; o < 4; o <<= 1) {
            psA[h] += __shfl_xor_sync(0xffffffffu, psA[h], o);
            psB[h] += __shfl_xor_sync(0xffffffffu, psB[h], o);
            pdA[h] += __shfl_xor_sync(0xffffffffu, pdA[h], o);
            pdB[h] += __shfl_xor_sync(0xffffffffu, pdB[h], o);
        }
    }
    int lr = warp_m * 16 + (lane >> 2);
    __syncthreads();
    if (warp_n == 1 && (lane & 3) == 0) {
#pragma unroll
        for (int h = 0; h < 4; h++) {
            sRs[lr][h] = psA[h];     sRd[lr][h] = pdA[h];
            sRs[lr + 8][h] = psB[h]; sRd[lr + 8][h] = pdB[h];
        }
    }
    __syncthreads();
    if (warp_n == 0 && (lane & 3) == 0) {
        if (rowA < N_NODES) {
#pragma unroll
            for (int h = 0; h < 4; h++) {
                g_asrc[rowA * HEADS + h] = psA[h] + sRs[lr][h];
                g_adst[rowA * HEADS + h] = pdA[h] + sRd[lr][h];
            }
        }
        if (rowA + 8 < N_NODES) {
#pragma unroll
            for (int h = 0; h < 4; h++) {
                g_asrc[(rowA + 8) * HEADS + h] = psB[h] + sRs[lr + 8][h];
                g_adst[(rowA + 8) * HEADS + h] = pdB[h] + sRd[lr + 8][h];
            }
        }
    }
}

// ---------------- per-node softmax + weighted aggregation ----------------
__device__ __forceinline__ float leaky(float e) { return e > 0.f ? e : NEG_SLOPE * e; }

__device__ __forceinline__ void acc8(float* acc, uint4 v, float al) {
    float2 f0 = __half22float2(*(__half2*)&v.x);
    float2 f1 = __half22float2(*(__half2*)&v.y);
    float2 f2 = __half22float2(*(__half2*)&v.z);
    float2 f3 = __half22float2(*(__half2*)&v.w);
    acc[0] += f0.x * al; acc[1] += f0.y * al;
    acc[2] += f1.x * al; acc[3] += f1.y * al;
    acc[4] += f2.x * al; acc[5] += f2.y * al;
    acc[6] += f3.x * al; acc[7] += f3.y * al;
}

__global__ __launch_bounds__(128) void agg_k(const float* __restrict__ gat_bias) {
    __shared__ int   sadj[CAP];
    __shared__ float se[HEADS][CAP];
    __shared__ float sinv[HEADS], sadh[HEADS];
    __shared__ float swsum[4][HEADS];
    __shared__ float sacc[64][9];
    int d = blockIdx.x;
    int tid = threadIdx.x;
    int w = tid >> 5, lane = tid & 31;
    int beg = g_off[d];
    int deg = g_off[d + 1] - beg;
    bool cached = (deg <= CAP);
    float4 adv = *(const float4*)&g_adst[d * HEADS];

    float s0 = 0.f, s1 = 0.f, s2 = 0.f, s3 = 0.f;
    if (cached) {
        for (int i = tid; i < deg; i += 128) {
            int s = g_adj[beg + i];
            sadj[i] = s;
            float4 as = *(const float4*)&g_asrc[s * HEADS];
            float a0 = __expf(leaky(as.x + adv.x)); se[0][i] = a0; s0 += a0;
            float a1 = __expf(leaky(as.y + adv.y)); se[1][i] = a1; s1 += a1;
            float a2 = __expf(leaky(as.z + adv.z)); se[2][i] = a2; s2 += a2;
            float a3 = __expf(leaky(as.w + adv.w)); se[3][i] = a3; s3 += a3;
        }
    } else {
        for (int i = tid; i < deg; i += 128) {
            int s = g_adj[beg + i];
            float4 as = *(const float4*)&g_asrc[s * HEADS];
            s0 += __expf(leaky(as.x + adv.x));
            s1 += __expf(leaky(as.y + adv.y));
            s2 += __expf(leaky(as.z + adv.z));
            s3 += __expf(leaky(as.w + adv.w));
        }
    }
#pragma unroll
    for (int o = 16; o; o >>= 1) {
        s0 += __shfl_xor_sync(0xffffffffu, s0, o);
        s1 += __shfl_xor_sync(0xffffffffu, s1, o);
        s2 += __shfl_xor_sync(0xffffffffu, s2, o);
        s3 += __shfl_xor_sync(0xffffffffu, s3, o);
    }
    if (lane == 0) {
        swsum[w][0] = s0; swsum[w][1] = s1;
        swsum[w][2] = s2; swsum[w][3] = s3;
    }
    if (tid < HEADS) {
        float v = tid == 0 ? adv.x : tid == 1 ? adv.y : tid == 2 ? adv.z : adv.w;
        sadh[tid] = v;
    }
    __syncthreads();
    if (tid < HEADS) {
        float t = swsum[0][tid] + swsum[1][tid] + swsum[2][tid] + swsum[3][tid];
        sinv[tid] = 1.f / (t + 1e-16f);
    }
    __syncthreads();

    int g = tid >> 6;
    int t6 = tid & 63;
    int ch = t6 * 8;
    int head = t6 >> 4;
    float inv = sinv[head];
    float acc[8] = {0.f, 0.f, 0.f, 0.f, 0.f, 0.f, 0.f, 0.f};
    const __half* hbase = g_h16;

    if (cached) {
        int i = g;
        for (; i + 6 < deg; i += 8) {
            float al0 = se[head][i] * inv;
            float al1 = se[head][i + 2] * inv;
            float al2 = se[head][i + 4] * inv;
            float al3 = se[head][i + 6] * inv;
            uint4 v0 = *(const uint4*)&hbase[(size_t)sadj[i]     * HID + ch];
            uint4 v1 = *(const uint4*)&hbase[(size_t)sadj[i + 2] * HID + ch];
            uint4 v2 = *(const uint4*)&hbase[(size_t)sadj[i + 4] * HID + ch];
            uint4 v3 = *(const uint4*)&hbase[(size_t)sadj[i + 6] * HID + ch];
            acc8(acc, v0, al0);
            acc8(acc, v1, al1);
            acc8(acc, v2, al2);
            acc8(acc, v3, al3);
        }
        for (; i < deg; i += 2) {
            float al = se[head][i] * inv;
            uint4 v = *(const uint4*)&hbase[(size_t)sadj[i] * HID + ch];
            acc8(acc, v, al);
        }
    } else {
        float adhh = sadh[head];
        for (int i = g; i < deg; i += 2) {
            int s = g_adj[beg + i];
            float al = __expf(leaky(g_asrc[s * HEADS + head] + adhh)) * inv;
            uint4 v = *(const uint4*)&hbase[(size_t)s * HID + ch];
            acc8(acc, v, al);
        }
    }

    if (g == 1) {
#pragma unroll
        for (int j = 0; j < 8; j++) sacc[t6][j] = acc[j];
    }
    __syncthreads();
    if (g == 0) {
        float4 b0 = *(const float4*)&gat_bias[ch];
        float4 b1 = *(const float4*)&gat_bias[ch + 4];
        float r0 = fmaxf(acc[0] + sacc[t6][0] + b0.x, 0.f);
        float r1 = fmaxf(acc[1] + sacc[t6][1] + b0.y, 0.f);
        float r2 = fmaxf(acc[2] + sacc[t6][2] + b0.z, 0.f);
        float r3 = fmaxf(acc[3] + sacc[t6][3] + b0.w, 0.f);
        float r4 = fmaxf(acc[4] + sacc[t6][4] + b1.x, 0.f);
        float r5 = fmaxf(acc[5] + sacc[t6][5] + b1.y, 0.f);
        float r6 = fmaxf(acc[6] + sacc[t6][6] + b1.z, 0.f);
        float r7 = fmaxf(acc[7] + sacc[t6][7] + b1.w, 0.f);
        uint4 st;
        *(__half2*)&st.x = __floats2half2_rn(r0, r1);
        *(__half2*)&st.y = __floats2half2_rn(r2, r3);
        *(__half2*)&st.z = __floats2half2_rn(r4, r5);
        *(__half2*)&st.w = __floats2half2_rn(r6, r7);
        *(uint4*)&g_act16[(size_t)d * HID + ch] = st;
    }
}

// ------- GEMM2 (fp16 mma, 64-K chunks) + bias + residual + register LN ---
__global__ __launch_bounds__(256) void gemm2_ln_k(const float* __restrict__ proj_b,
                                                  const float* __restrict__ x,
                                                  const float* __restrict__ lng,
                                                  const float* __restrict__ lnb,
                                                  float* __restrict__ out) {
    __shared__ uint32_t sA[64 * 36];        // 9 KB
    __shared__ uint32_t sB[32 * 136];       // 17 KB
    __shared__ float sP1[2][64], sP2[2][64];// 1 KB LN partials per warp_n
    int tid = threadIdx.x;
    int lane = tid & 31, wid = tid >> 5;
    int warp_m = wid & 3, warp_n = wid >> 2;
    int m0 = blockIdx.x * 64;

    float c[8][4];
#pragma unroll
    for (int nt = 0; nt < 8; nt++)
#pragma unroll
        for (int r = 0; r < 4; r++) c[nt][r] = 0.f;

    int aRow = warp_m * 16 + (lane >> 2);
    int kq = lane & 3;

    for (int kc = 0; kc < HID; kc += 64) {
        __syncthreads();
#pragma unroll
        for (int p = 0; p < 4; p++) {
            int idx = tid + p * 256;
            int row = idx >> 4, h2 = (idx & 15) * 2;
            int gr = m0 + row;
            uint2 v = (gr < N_NODES)
                ? *(const uint2*)&g_act16[(size_t)gr * HID + kc + h2 * 2]
                : make_uint2(0u, 0u);
            sA[row * 36 + h2] = v.x;
            sA[row * 36 + h2 + 1] = v.y;
        }
#pragma unroll
        for (int p = 0; p < 4; p++) {
            int idx = tid + p * 256;
            int row = idx >> 5, q = (idx & 31) * 4;
            uint4 v = *(const uint4*)&g_w16[(size_t)(kc / 2 + row) * OUT_CH + q];
            *(uint4*)&sB[row * 136 + q] = v;
        }
        __syncthreads();

#pragma unroll
        for (int ks = 0; ks < 64; ks += 16) {
            int ho = ks >> 1;
            uint32_t a0 = sA[aRow * 36 + ho + kq];
            uint32_t a1 = sA[(aRow + 8) * 36 + ho + kq];
            uint32_t a2 = sA[aRow * 36 + ho + kq + 4];
            uint32_t a3 = sA[(aRow + 8) * 36 + ho + kq + 4];
#pragma unroll
            for (int nt = 0; nt < 8; nt++) {
                int nb = warp_n * 64 + nt * 8 + (lane >> 2);
                uint32_t b0 = sB[(ho + kq) * 136 + nb];
                uint32_t b1 = sB[(ho + kq + 4) * 136 + nb];
                asm volatile(
                    "mma.sync.aligned.m16n8k16.row.col.f32.f16.f16.f32 "
                    "{%0,%1,%2,%3}, {%4,%5,%6,%7}, {%8,%9}, {%0,%1,%2,%3};"
                    : "+f"(c[nt][0]), "+f"(c[nt][1]), "+f"(c[nt][2]), "+f"(c[nt][3])
                    : "r"(a0), "r"(a1), "r"(a2), "r"(a3), "r"(b0), "r"(b1));
            }
        }
    }

    int lr = warp_m * 16 + (lane >> 2);
    int gr0 = m0 + lr, gr1 = gr0 + 8;
    float s1r0 = 0.f, s2r0 = 0.f, s1r1 = 0.f, s2r1 = 0.f;
#pragma unroll
    for (int nt = 0; nt < 8; nt++) {
        int col = warp_n * 64 + nt * 8 + (lane & 3) * 2;
        float pb0 = proj_b[col], pb1 = proj_b[col + 1];
        float x00 = 0.f, x01 = 0.f, x10 = 0.f, x11 = 0.f;
        if (gr0 < N_NODES) {
            x00 = x[(size_t)gr0 * OUT_CH + col];
            x01 = x[(size_t)gr0 * OUT_CH + col + 1];
        }
        if (gr1 < N_NODES) {
            x10 = x[(size_t)gr1 * OUT_CH + col];
            x11 = x[(size_t)gr1 * OUT_CH + col + 1];
        }
        c[nt][0] += pb0 + x00;
        c[nt][1] += pb1 + x01;
        c[nt][2] += pb0 + x10;
        c[nt][3] += pb1 + x11;
        s1r0 += c[nt][0] + c[nt][1];
        s2r0 += c[nt][0] * c[nt][0] + c[nt][1] * c[nt][1];
        s1r1 += c[nt][2] + c[nt][3];
        s2r1 += c[nt][2] * c[nt][2] + c[nt][3] * c[nt][3];
    }
#pragma unroll
    for (int o = 1; o < 4; o <<= 1) {
        s1r0 += __shfl_xor_sync(0xffffffffu, s1r0, o);
        s2r0 += __shfl_xor_sync(0xffffffffu, s2r0, o);
        s1r1 += __shfl_xor_sync(0xffffffffu, s1r1, o);
        s2r1 += __shfl_xor_sync(0xffffffffu, s2r1, o);
    }
    __syncthreads();
    if ((lane & 3) == 0) {
        sP1[warp_n][lr] = s1r0;     sP2[warp_n][lr] = s2r0;
        sP1[warp_n][lr + 8] = s1r1; sP2[warp_n][lr + 8] = s2r1;
    }
    __syncthreads();
    float t1r0 = sP1[0][lr] + sP1[1][lr];
    float t2r0 = sP2[0][lr] + sP2[1][lr];
    float t1r1 = sP1[0][lr + 8] + sP1[1][lr + 8];
    float t2r1 = sP2[0][lr + 8] + sP2[1][lr + 8];
    float mu0 = t1r0 * (1.f / 128.f);
    float rs0 = rsqrtf(t2r0 * (1.f / 128.f) - mu0 * mu0 + LN_EPS);
    float mu1 = t1r1 * (1.f / 128.f);
    float rs1 = rsqrtf(t2r1 * (1.f / 128.f) - mu1 * mu1 + LN_EPS);

#pragma unroll
    for (int nt = 0; nt < 8; nt++) {
        int col = warp_n * 64 + nt * 8 + (lane & 3) * 2;
        float g0 = lng[col], g1 = lng[col + 1];
        float b0 = lnb[col], b1 = lnb[col + 1];
        if (gr0 < N_NODES) {
            float2 o0 = make_float2((c[nt][0] - mu0) * rs0 * g0 + b0,
                                    (c[nt][1] - mu0) * rs0 * g1 + b1);
            *(float2*)&out[(size_t)gr0 * OUT_CH + col] = o0;
        }
        if (gr1 < N_NODES) {
            float2 o1 = make_float2((c[nt][2] - mu1) * rs1 * g0 + b0,
                                    (c[nt][3] - mu1) * rs1 * g1 + b1);
            *(float2*)&out[(size_t)gr1 * OUT_CH + col] = o1;
        }
    }
}

// ----- launch: CSR on main stream (critical path), GEMM1 on side --------
extern "C" void kernel_launch(void* const* d_in, const int* in_sizes, int n_in,
                              void* d_out, int out_size) {
    const float* x        = (const float*)d_in[0];
    const void*  ei       = d_in[1];
    const float* lin_w    = (const float*)d_in[2];
    const float* att_src  = (const float*)d_in[3];
    const float* att_dst  = (const float*)d_in[4];
    const float* gat_bias = (const float*)d_in[5];
    const float* proj_w   = (const float*)d_in[6];
    const float* proj_b   = (const float*)d_in[7];
    const float* ln_g     = (const float*)d_in[8];
    const float* ln_b     = (const float*)d_in[9];
    float* out = (float*)d_out;

    void* cnt_ptr = nullptr;
    cudaGetSymbolAddress(&cnt_ptr, g_cnt);

    cudaStream_t sc;
    cudaEvent_t evF, evJ;
    cudaStreamCreateWithFlags(&sc, cudaStreamNonBlocking);
    cudaEventCreateWithFlags(&evF, cudaEventDisableTiming);
    cudaEventCreateWithFlags(&evJ, cudaEventDisableTiming);

    cudaEventRecord(evF, 0);
    cudaStreamWaitEvent(sc, evF, 0);

    // ---- side stream: feature path (attn fused into gemm1) + wconv ----
    lwconv_k<<<((IN_CH / 2) * HID + 255) / 256, 256, 0, sc>>>(lin_w);
    gemm1_k<<<(N_NODES + 63) / 64, 256, 0, sc>>>(x, att_src, att_dst);
    wconv_k<<<((HID / 2) * OUT_CH + 255) / 256, 256, 0, sc>>>(proj_w);
    cudaEventRecord(evJ, sc);

    // ---- main stream: CSR build (the critical path) ----
    cudaMemsetAsync(cnt_ptr, 0, N_NODES * sizeof(int), 0);
    detect_k<<<1, 256>>>(ei);
    hist_k<<<(N_EDGES + 511) / 512, 512>>>(ei);
    partial_k<<<NPART, SCAN_BLK>>>();
    scanoff_k<<<NPART, SCAN_BLK>>>();
    scatter_k<<<(N_EDGES + 511) / 512, 512>>>(ei);

    cudaStreamWaitEvent(0, evJ, 0);
    agg_k<<<N_NODES, 128>>>(gat_bias);
    gemm2_ln_k<<<(N_NODES + 63) / 64, 256>>>(proj_b, x, ln_g, ln_b, out);
}